// round 8
// baseline (speedup 1.0000x reference)
#include <cuda_runtime.h>

#define N_NODES 61440
#define NB      2048
#define NT      30
#define E_EDGES 491520

// packed f32x2 helpers (sm_103a)
#define FFMA2(acc, a, b) \
    asm("fma.rn.f32x2 %0, %1, %2, %0;" : "+l"(acc) : "l"(a), "l"(b))
#define DUP2(out, w) \
    asm("mov.b64 %0, {%1, %1};" : "=l"(out) : "r"(__float_as_uint(w)))
#define UNPACK2(lo, hi, in) \
    asm("mov.b64 {%0, %1}, %2;" : "=f"(lo), "=f"(hi) : "l"(in))

// ---------------- scratch (device globals; no runtime allocation) ----------
__device__ float g_deg [N_NODES];
__device__ float g_dinv[N_NODES];
__device__ float g_h   [N_NODES * 12];
__device__ float g_acc [N_NODES * 12];
__device__ float g_X0  [NB * 12  * NT];
__device__ float g_X1  [NB * 128 * NT];
__device__ float g_X2  [NB * 512 * NT];
__device__ float g_X3  [NB * 128 * NT];

// ---------------- GCN ------------------------------------------------------
__global__ void k_init_deg() {
    int i = blockIdx.x * blockDim.x + threadIdx.x;
    if (i < N_NODES) g_deg[i] = 1.0f;   // self-loop
}

// edge_index is int32 (JAX x64 disabled downcasts jnp.int64 -> int32)
__global__ void k_count(const int* __restrict__ ei) {
    int e = blockIdx.x * blockDim.x + threadIdx.x;
    if (e < E_EDGES) {
        int dst = ei[E_EDGES + e];
        atomicAdd(&g_deg[dst], 1.0f);
    }
}

__global__ void k_h(const float* __restrict__ x, const float* __restrict__ w) {
    int n = blockIdx.x * blockDim.x + threadIdx.x;
    if (n >= N_NODES) return;
    float xv[12];
#pragma unroll
    for (int j = 0; j < 12; j++) xv[j] = x[n * 12 + j];
    float dinv = rsqrtf(g_deg[n]);
    g_dinv[n] = dinv;
    float s = dinv * dinv;
#pragma unroll
    for (int c = 0; c < 12; c++) {
        float acc = 0.f;
#pragma unroll
        for (int j = 0; j < 12; j++) acc += xv[j] * __ldg(&w[c * 12 + j]);
        g_h[n * 12 + c]   = acc;
        g_acc[n * 12 + c] = s * acc;    // self-loop contribution
    }
}

__global__ void k_scatter(const int* __restrict__ ei) {
    int e = blockIdx.x * blockDim.x + threadIdx.x;
    if (e >= E_EDGES) return;
    int src = ei[e];
    int dst = ei[E_EDGES + e];
    float norm = g_dinv[src] * g_dinv[dst];
    const float4* hs = (const float4*)&g_h[src * 12];
    float4 a = hs[0], b = hs[1], c = hs[2];
    float* ad = &g_acc[dst * 12];
    atomicAdd(ad + 0,  norm * a.x);  atomicAdd(ad + 1,  norm * a.y);
    atomicAdd(ad + 2,  norm * a.z);  atomicAdd(ad + 3,  norm * a.w);
    atomicAdd(ad + 4,  norm * b.x);  atomicAdd(ad + 5,  norm * b.y);
    atomicAdd(ad + 6,  norm * b.z);  atomicAdd(ad + 7,  norm * b.w);
    atomicAdd(ad + 8,  norm * c.x);  atomicAdd(ad + 9,  norm * c.y);
    atomicAdd(ad + 10, norm * c.z);  atomicAdd(ad + 11, norm * c.w);
}

// node-major [n][c] -> [b][c][t] layout for TCN, add bias
__global__ void k_trans(const float* __restrict__ gb) {
    int i = blockIdx.x * blockDim.x + threadIdx.x;
    if (i >= NB * 12 * NT) return;
    int b = i / (12 * NT);
    int r = i - b * 12 * NT;
    int c = r / NT;
    int t = r - c * NT;
    g_X0[i] = g_acc[(b * NT + t) * 12 + c] + gb[c];
}

// ---------------- TCN block (f32x2 packed over batch pairs) ---------------
// out = relu( relu(conv_dilated(X)+cb) + (down1x1(X)+db) )
// grid: (NB/4, COUT/128), block 256 = 128 co x 2 batch-pairs (4 batches/CTA)
template <int CIN, int COUT, int DIL, int CICH>
__global__ void __launch_bounds__(256, 1)
k_tcn2(const float* __restrict__ Xin,
       const float* __restrict__ cw, const float* __restrict__ cb,
       const float* __restrict__ dw, const float* __restrict__ db,
       float* __restrict__ Xout) {
    extern __shared__ float sm[];
    float*  ws = sm;                            // [CICH][4][128] : k0,k1,k2,down
    float2* xs = (float2*)(sm + CICH * 4 * 128); // [2 pairs][CICH][NT]
    const int tid = threadIdx.x;
    const int cow = tid & 127;
    const int g   = tid >> 7;                   // batch-pair index 0/1
    const int co  = blockIdx.y * 128 + cow;
    const int b0  = blockIdx.x * 4;

    unsigned long long accC[NT], accD[NT];
#pragma unroll
    for (int t = 0; t < NT; t++) { accC[t] = 0ull; accD[t] = 0ull; }

    for (int ci0 = 0; ci0 < CIN; ci0 += CICH) {
        __syncthreads();
        // stage conv weights (coalesced global reads, conflict-free smem)
        for (int e = tid; e < 128 * CICH * 3; e += 256) {
            int co_ = e / (CICH * 3);
            int r   = e - co_ * (CICH * 3);
            int ci  = r / 3, k = r - ci * 3;
            ws[(ci * 4 + k) * 128 + co_] =
                cw[((blockIdx.y * 128 + co_) * CIN + ci0 + ci) * 3 + k];
        }
        // stage downsample weights
        for (int e = tid; e < 128 * CICH; e += 256) {
            int co_ = e / CICH;
            int ci  = e - co_ * CICH;
            ws[(ci * 4 + 3) * 128 + co_] =
                dw[(blockIdx.y * 128 + co_) * CIN + ci0 + ci];
        }
        // stage input as batch-pair-interleaved float2
        for (int e = tid; e < 2 * CICH * NT; e += 256) {
            int g_ = e / (CICH * NT);
            int r  = e - g_ * (CICH * NT);
            int ci = r / NT, t = r - ci * NT;
            long base = (long)(b0 + 2 * g_) * CIN * NT + (ci0 + ci) * NT + t;
            xs[e] = make_float2(Xin[base], Xin[base + CIN * NT]);
        }
        __syncthreads();

#pragma unroll 2
        for (int ci = 0; ci < CICH; ci++) {
            float w0 = ws[(ci * 4 + 0) * 128 + cow];
            float w1 = ws[(ci * 4 + 1) * 128 + cow];
            float w2 = ws[(ci * 4 + 2) * 128 + cow];
            float wd = ws[(ci * 4 + 3) * 128 + cow];
            unsigned long long W0, W1, W2, WD;
            DUP2(W0, w0); DUP2(W1, w1); DUP2(W2, w2); DUP2(WD, wd);
            const float2* xr = &xs[(g * CICH + ci) * NT];
#pragma unroll
            for (int t = 0; t < NT; t += 2) {
                ulonglong2 xq = *(const ulonglong2*)(xr + t);   // (t, t+1) pairs
                FFMA2(accD[t],     WD, xq.x);
                FFMA2(accD[t + 1], WD, xq.y);
                FFMA2(accC[t],     W2, xq.x);                   // tap k=2 -> +0
                FFMA2(accC[t + 1], W2, xq.y);
                if (t + DIL < NT)         FFMA2(accC[t + DIL],         W1, xq.x);
                if (t + 1 + DIL < NT)     FFMA2(accC[t + 1 + DIL],     W1, xq.y);
                if (t + 2 * DIL < NT)     FFMA2(accC[t + 2 * DIL],     W0, xq.x);
                if (t + 1 + 2 * DIL < NT) FFMA2(accC[t + 1 + 2 * DIL], W0, xq.y);
            }
        }
    }

    float cbv = cb[co], dbv = db[co];
    float* outA = &Xout[(long)(b0 + 2 * g) * COUT * NT + co * NT];
    float* outB = outA + (long)COUT * NT;
#pragma unroll
    for (int t = 0; t < NT; t++) {
        float cA, cB, dA, dB;
        UNPACK2(cA, cB, accC[t]);
        UNPACK2(dA, dB, accD[t]);
        outA[t] = fmaxf(fmaxf(cA + cbv, 0.0f) + dA + dbv, 0.0f);
        outB[t] = fmaxf(fmaxf(cB + cbv, 0.0f) + dB + dbv, 0.0f);
    }
}

// ---------------- FC -------------------------------------------------------
// out[b][o] = sum_j X3[b][j] * fw[o][j] + fb[o], j = c*30+t (matches layout)
__global__ void k_fc(const float* __restrict__ X, const float* __restrict__ fw,
                     const float* __restrict__ fb, float* __restrict__ out) {
    extern __shared__ float xs[];            // [8][3840]
    const int tid = threadIdx.x;
    const int b0  = blockIdx.x * 8;
    for (int e = tid; e < 8 * 3840; e += 256)
        xs[e] = X[(long)b0 * 3840 + e];
    __syncthreads();

    const int w    = tid >> 5;
    const int lane = tid & 31;
    const int o0   = w * 9;
    float acc[9][8];
#pragma unroll
    for (int r = 0; r < 9; r++)
#pragma unroll
        for (int g2 = 0; g2 < 8; g2++) acc[r][g2] = 0.f;

    for (int it = 0; it < 120; it++) {
        int j = it * 32 + lane;
        float xj[8];
#pragma unroll
        for (int g2 = 0; g2 < 8; g2++) xj[g2] = xs[g2 * 3840 + j];
#pragma unroll
        for (int r = 0; r < 9; r++) {
            float wv = fw[(o0 + r) * 3840 + j];
#pragma unroll
            for (int g2 = 0; g2 < 8; g2++) acc[r][g2] += wv * xj[g2];
        }
    }
#pragma unroll
    for (int r = 0; r < 9; r++) {
#pragma unroll
        for (int g2 = 0; g2 < 8; g2++) {
            float v = acc[r][g2];
            for (int off = 16; off; off >>= 1)
                v += __shfl_xor_sync(0xffffffff, v, off);
            if (lane == 0)
                out[(b0 + g2) * 72 + o0 + r] = v + fb[o0 + r];
        }
    }
}

// ---------------- launch ---------------------------------------------------
extern "C" void kernel_launch(void* const* d_in, const int* in_sizes, int n_in,
                              void* d_out, int out_size) {
    const float* x   = (const float*)d_in[0];
    const int*   ei  = (const int*)d_in[1];     // int32
    const float* gw  = (const float*)d_in[2];
    const float* gb  = (const float*)d_in[3];
    const float* cw0 = (const float*)d_in[4];
    const float* cb0 = (const float*)d_in[5];
    const float* dw0 = (const float*)d_in[6];
    const float* db0 = (const float*)d_in[7];
    const float* cw1 = (const float*)d_in[8];
    const float* cb1 = (const float*)d_in[9];
    const float* dw1 = (const float*)d_in[10];
    const float* db1 = (const float*)d_in[11];
    const float* cw2 = (const float*)d_in[12];
    const float* cb2 = (const float*)d_in[13];
    const float* dw2 = (const float*)d_in[14];
    const float* db2 = (const float*)d_in[15];
    const float* fw  = (const float*)d_in[16];
    const float* fb  = (const float*)d_in[17];
    float* out = (float*)d_out;

    float *pX0, *pX1, *pX2, *pX3;
    cudaGetSymbolAddress((void**)&pX0, g_X0);
    cudaGetSymbolAddress((void**)&pX1, g_X1);
    cudaGetSymbolAddress((void**)&pX2, g_X2);
    cudaGetSymbolAddress((void**)&pX3, g_X3);

    // dynamic smem opt-in (idempotent; done every call)
    const int smem0 = (12 * 4 * 128) * 4 + 2 * 12 * NT * 8;   // 30336
    const int smem1 = (32 * 4 * 128) * 4 + 2 * 32 * NT * 8;   // 80896
    const int smemF = 8 * 3840 * 4;                           // 122880
    cudaFuncSetAttribute(k_tcn2<128, 512, 3, 32>,
                         cudaFuncAttributeMaxDynamicSharedMemorySize, smem1);
    cudaFuncSetAttribute(k_tcn2<512, 128, 9, 32>,
                         cudaFuncAttributeMaxDynamicSharedMemorySize, smem1);
    cudaFuncSetAttribute(k_fc,
                         cudaFuncAttributeMaxDynamicSharedMemorySize, smemF);

    // ---- GCN ----
    k_init_deg<<<(N_NODES + 255) / 256, 256>>>();
    k_count<<<(E_EDGES + 255) / 256, 256>>>(ei);
    k_h<<<(N_NODES + 255) / 256, 256>>>(x, gw);
    k_scatter<<<(E_EDGES + 255) / 256, 256>>>(ei);
    k_trans<<<(NB * 12 * NT + 255) / 256, 256>>>(gb);

    // ---- TCN (f32x2 packed) ----
    k_tcn2<12, 128, 1, 12><<<dim3(NB / 4, 1), 256, smem0>>>(pX0, cw0, cb0, dw0, db0, pX1);
    k_tcn2<128, 512, 3, 32><<<dim3(NB / 4, 4), 256, smem1>>>(pX1, cw1, cb1, dw1, db1, pX2);
    k_tcn2<512, 128, 9, 32><<<dim3(NB / 4, 1), 256, smem1>>>(pX2, cw2, cb2, dw2, db2, pX3);

    // ---- FC (final relu is identity: X3 >= 0 already) ----
    k_fc<<<NB / 8, 256, smemF>>>(pX3, fw, fb, out);
}

// round 9
// speedup vs baseline: 1.0231x; 1.0231x over previous
#include <cuda_runtime.h>

#define N_NODES 61440
#define NB      2048
#define NT      30
#define E_EDGES 491520

// packed f32x2 helpers (sm_103a)
#define FFMA2(acc, a, b) \
    asm("fma.rn.f32x2 %0, %1, %2, %0;" : "+l"(acc) : "l"(a), "l"(b))
#define DUP2(out, w) \
    asm("mov.b64 %0, {%1, %1};" : "=l"(out) : "r"(__float_as_uint(w)))
#define UNPACK2(lo, hi, in) \
    asm("mov.b64 {%0, %1}, %2;" : "=f"(lo), "=f"(hi) : "l"(in))

// ---------------- scratch (device globals; no runtime allocation) ----------
__device__ float g_deg [N_NODES];
__device__ float g_dinv[N_NODES];
__device__ float g_h   [N_NODES * 12];
__device__ float g_acc [N_NODES * 12];
__device__ float g_X0  [NB * 12  * NT];
__device__ float g_X1  [NB * 128 * NT];
__device__ float g_X2  [NB * 512 * NT];
__device__ float g_X3  [NB * 128 * NT];

// ---------------- GCN ------------------------------------------------------
__global__ void k_init_deg() {
    int i = blockIdx.x * blockDim.x + threadIdx.x;
    if (i < N_NODES) g_deg[i] = 1.0f;   // self-loop
}

// edge_index is int32 (JAX x64 disabled downcasts jnp.int64 -> int32)
__global__ void k_count(const int* __restrict__ ei) {
    int e = blockIdx.x * blockDim.x + threadIdx.x;
    if (e < E_EDGES) {
        int dst = ei[E_EDGES + e];
        atomicAdd(&g_deg[dst], 1.0f);
    }
}

__global__ void k_h(const float* __restrict__ x, const float* __restrict__ w) {
    int n = blockIdx.x * blockDim.x + threadIdx.x;
    if (n >= N_NODES) return;
    float xv[12];
#pragma unroll
    for (int j = 0; j < 12; j++) xv[j] = x[n * 12 + j];
    float dinv = rsqrtf(g_deg[n]);
    g_dinv[n] = dinv;
    float s = dinv * dinv;
#pragma unroll
    for (int c = 0; c < 12; c++) {
        float acc = 0.f;
#pragma unroll
        for (int j = 0; j < 12; j++) acc += xv[j] * __ldg(&w[c * 12 + j]);
        g_h[n * 12 + c]   = acc;
        g_acc[n * 12 + c] = s * acc;    // self-loop contribution
    }
}

__global__ void k_scatter(const int* __restrict__ ei) {
    int e = blockIdx.x * blockDim.x + threadIdx.x;
    if (e >= E_EDGES) return;
    int src = ei[e];
    int dst = ei[E_EDGES + e];
    float norm = g_dinv[src] * g_dinv[dst];
    const float4* hs = (const float4*)&g_h[src * 12];
    float4 a = hs[0], b = hs[1], c = hs[2];
    float* ad = &g_acc[dst * 12];
    atomicAdd(ad + 0,  norm * a.x);  atomicAdd(ad + 1,  norm * a.y);
    atomicAdd(ad + 2,  norm * a.z);  atomicAdd(ad + 3,  norm * a.w);
    atomicAdd(ad + 4,  norm * b.x);  atomicAdd(ad + 5,  norm * b.y);
    atomicAdd(ad + 6,  norm * b.z);  atomicAdd(ad + 7,  norm * b.w);
    atomicAdd(ad + 8,  norm * c.x);  atomicAdd(ad + 9,  norm * c.y);
    atomicAdd(ad + 10, norm * c.z);  atomicAdd(ad + 11, norm * c.w);
}

// node-major [n][c] -> [b][c][t] layout for TCN, add bias
__global__ void k_trans(const float* __restrict__ gb) {
    int i = blockIdx.x * blockDim.x + threadIdx.x;
    if (i >= NB * 12 * NT) return;
    int b = i / (12 * NT);
    int r = i - b * 12 * NT;
    int c = r / NT;
    int t = r - c * NT;
    g_X0[i] = g_acc[(b * NT + t) * 12 + c] + gb[c];
}

// ---------------- TCN chunk compute (compile-time t-window) ----------------
// Each thread accumulates outputs t in [T0, T0+15) for one co and one
// batch-pair (f32x2). Input-stationary over s; all acc indices compile-time.
template <int CICH, int DIL, int T0>
__device__ __forceinline__ void tcn_chunk(const float4* __restrict__ ws4,
                                          const unsigned long long* __restrict__ xr,
                                          int cow,
                                          unsigned long long accC[15],
                                          unsigned long long accD[15]) {
#pragma unroll 2
    for (int ci = 0; ci < CICH; ci++) {
        float4 w = ws4[ci * 128 + cow];          // w0, w1, w2, wd
        unsigned long long W0, W1, W2, WD;
        DUP2(W0, w.x); DUP2(W1, w.y); DUP2(W2, w.z); DUP2(WD, w.w);
        const unsigned long long* x = xr + ci * NT;
#pragma unroll
        for (int s = T0 - 2 * DIL; s < T0 + 15; s++) {
            if (s < 0) continue;                                   // compile-time
            const bool u2 = (s >= T0);                             // tap k=2 & down
            const bool u1 = (s + DIL >= T0) && (s + DIL < T0 + 15);
            const bool u0 = (s + 2 * DIL >= T0) && (s + 2 * DIL < T0 + 15);
            if (!(u2 || u1 || u0)) continue;
            unsigned long long xv = x[s];
            if (u2) { FFMA2(accD[s - T0], WD, xv); FFMA2(accC[s - T0], W2, xv); }
            if (u1) { FFMA2(accC[s + DIL - T0], W1, xv); }
            if (u0) { FFMA2(accC[s + 2 * DIL - T0], W0, xv); }
        }
    }
}

// ---------------- TCN block (f32x2 over batch pairs, split t-window) -------
// out = relu( relu(conv_dilated(X)+cb) + (down1x1(X)+db) )
// grid: (NB/4, COUT/128)  block 512 = 128 co x 2 t-halves x 2 batch-pairs
template <int CIN, int COUT, int DIL, int CICH>
__global__ void __launch_bounds__(512, 1)
k_tcn3(const float* __restrict__ Xin,
       const float* __restrict__ cw, const float* __restrict__ cb,
       const float* __restrict__ dw, const float* __restrict__ db,
       float* __restrict__ Xout) {
    extern __shared__ float sm[];
    float4* ws4 = (float4*)sm;                         // [CICH][128] float4
    unsigned long long* xs = (unsigned long long*)(sm + CICH * 4 * 128); // [2][CICH][NT] f32x2
    const int tid  = threadIdx.x;
    const int cow  = tid & 127;
    const int half = (tid >> 7) & 1;                   // t-window 0 / 15
    const int g    = tid >> 8;                         // batch-pair 0 / 1
    const int co   = blockIdx.y * 128 + cow;
    const int b0   = blockIdx.x * 4;

    unsigned long long accC[15], accD[15];
#pragma unroll
    for (int t = 0; t < 15; t++) { accC[t] = 0ull; accD[t] = 0ull; }

    for (int ci0 = 0; ci0 < CIN; ci0 += CICH) {
        __syncthreads();
        // stage weights as float4 (w0,w1,w2,wd) per (ci, co)
        for (int e = tid; e < 128 * CICH; e += 512) {
            int co_ = e & 127, ci = e >> 7;
            long wr = (long)(blockIdx.y * 128 + co_) * CIN + ci0 + ci;
            const float* cwp = &cw[wr * 3];
            ws4[e] = make_float4(cwp[0], cwp[1], cwp[2], dw[wr]);
        }
        // stage input as batch-pair-interleaved f32x2
        for (int e = tid; e < 2 * CICH * NT; e += 512) {
            int g_ = e / (CICH * NT);
            int r  = e - g_ * (CICH * NT);
            int ci = r / NT, t = r - ci * NT;
            long base = (long)(b0 + 2 * g_) * CIN * NT + (ci0 + ci) * NT + t;
            float2 v = make_float2(Xin[base], Xin[base + CIN * NT]);
            xs[e] = *(unsigned long long*)&v;
        }
        __syncthreads();

        const unsigned long long* xr = &xs[g * CICH * NT];
        if (half == 0) tcn_chunk<CICH, DIL, 0 >(ws4, xr, cow, accC, accD);
        else           tcn_chunk<CICH, DIL, 15>(ws4, xr, cow, accC, accD);
    }

    float cbv = cb[co], dbv = db[co];
    const int t0 = half * 15;
    float* outA = &Xout[(long)(b0 + 2 * g) * COUT * NT + co * NT + t0];
    float* outB = outA + (long)COUT * NT;
#pragma unroll
    for (int t = 0; t < 15; t++) {
        float cA, cB, dA, dB;
        UNPACK2(cA, cB, accC[t]);
        UNPACK2(dA, dB, accD[t]);
        outA[t] = fmaxf(fmaxf(cA + cbv, 0.0f) + dA + dbv, 0.0f);
        outB[t] = fmaxf(fmaxf(cB + cbv, 0.0f) + dB + dbv, 0.0f);
    }
}

// ---------------- FC -------------------------------------------------------
// out[b][o] = sum_j X3[b][j] * fw[o][j] + fb[o], j = c*30+t (matches layout)
__global__ void k_fc(const float* __restrict__ X, const float* __restrict__ fw,
                     const float* __restrict__ fb, float* __restrict__ out) {
    extern __shared__ float xs[];            // [8][3840]
    const int tid = threadIdx.x;
    const int b0  = blockIdx.x * 8;
    for (int e = tid; e < 8 * 3840; e += 256)
        xs[e] = X[(long)b0 * 3840 + e];
    __syncthreads();

    const int w    = tid >> 5;
    const int lane = tid & 31;
    const int o0   = w * 9;
    float acc[9][8];
#pragma unroll
    for (int r = 0; r < 9; r++)
#pragma unroll
        for (int g2 = 0; g2 < 8; g2++) acc[r][g2] = 0.f;

    for (int it = 0; it < 120; it++) {
        int j = it * 32 + lane;
        float xj[8];
#pragma unroll
        for (int g2 = 0; g2 < 8; g2++) xj[g2] = xs[g2 * 3840 + j];
#pragma unroll
        for (int r = 0; r < 9; r++) {
            float wv = fw[(o0 + r) * 3840 + j];
#pragma unroll
            for (int g2 = 0; g2 < 8; g2++) acc[r][g2] += wv * xj[g2];
        }
    }
#pragma unroll
    for (int r = 0; r < 9; r++) {
#pragma unroll
        for (int g2 = 0; g2 < 8; g2++) {
            float v = acc[r][g2];
            for (int off = 16; off; off >>= 1)
                v += __shfl_xor_sync(0xffffffff, v, off);
            if (lane == 0)
                out[(b0 + g2) * 72 + o0 + r] = v + fb[o0 + r];
        }
    }
}

// ---------------- launch ---------------------------------------------------
extern "C" void kernel_launch(void* const* d_in, const int* in_sizes, int n_in,
                              void* d_out, int out_size) {
    const float* x   = (const float*)d_in[0];
    const int*   ei  = (const int*)d_in[1];     // int32
    const float* gw  = (const float*)d_in[2];
    const float* gb  = (const float*)d_in[3];
    const float* cw0 = (const float*)d_in[4];
    const float* cb0 = (const float*)d_in[5];
    const float* dw0 = (const float*)d_in[6];
    const float* db0 = (const float*)d_in[7];
    const float* cw1 = (const float*)d_in[8];
    const float* cb1 = (const float*)d_in[9];
    const float* dw1 = (const float*)d_in[10];
    const float* db1 = (const float*)d_in[11];
    const float* cw2 = (const float*)d_in[12];
    const float* cb2 = (const float*)d_in[13];
    const float* dw2 = (const float*)d_in[14];
    const float* db2 = (const float*)d_in[15];
    const float* fw  = (const float*)d_in[16];
    const float* fb  = (const float*)d_in[17];
    float* out = (float*)d_out;

    float *pX0, *pX1, *pX2, *pX3;
    cudaGetSymbolAddress((void**)&pX0, g_X0);
    cudaGetSymbolAddress((void**)&pX1, g_X1);
    cudaGetSymbolAddress((void**)&pX2, g_X2);
    cudaGetSymbolAddress((void**)&pX3, g_X3);

    // dynamic smem opt-in (idempotent; done every call)
    const int smem0 = (12 * 4 * 128) * 4 + 2 * 12 * NT * 8;   // 30336
    const int smem1 = (32 * 4 * 128) * 4 + 2 * 32 * NT * 8;   // 80896
    const int smemF = 8 * 3840 * 4;                           // 122880
    cudaFuncSetAttribute(k_tcn3<128, 512, 3, 32>,
                         cudaFuncAttributeMaxDynamicSharedMemorySize, smem1);
    cudaFuncSetAttribute(k_tcn3<512, 128, 9, 32>,
                         cudaFuncAttributeMaxDynamicSharedMemorySize, smem1);
    cudaFuncSetAttribute(k_fc,
                         cudaFuncAttributeMaxDynamicSharedMemorySize, smemF);

    // ---- GCN ----
    k_init_deg<<<(N_NODES + 255) / 256, 256>>>();
    k_count<<<(E_EDGES + 255) / 256, 256>>>(ei);
    k_h<<<(N_NODES + 255) / 256, 256>>>(x, gw);
    k_scatter<<<(E_EDGES + 255) / 256, 256>>>(ei);
    k_trans<<<(NB * 12 * NT + 255) / 256, 256>>>(gb);

    // ---- TCN (f32x2 packed, split t-window, 16 warps/CTA) ----
    k_tcn3<12, 128, 1, 12><<<dim3(NB / 4, 1), 512, smem0>>>(pX0, cw0, cb0, dw0, db0, pX1);
    k_tcn3<128, 512, 3, 32><<<dim3(NB / 4, 4), 512, smem1>>>(pX1, cw1, cb1, dw1, db1, pX2);
    k_tcn3<512, 128, 9, 32><<<dim3(NB / 4, 1), 512, smem1>>>(pX2, cw2, cb2, dw2, db2, pX3);

    // ---- FC (final relu is identity: X3 >= 0 already) ----
    k_fc<<<NB / 8, 256, smemF>>>(pX3, fw, fb, out);
}

// round 13
// speedup vs baseline: 1.8323x; 1.7909x over previous
#include <cuda_runtime.h>
#include <cuda_bf16.h>
#include <cstdint>

#define N_NODES 61440
#define NB      2048
#define NT      30
#define E_EDGES 491520

// ---------------- scratch (device globals; no runtime allocation) ----------
__device__ float g_deg [N_NODES];
__device__ float g_dinv[N_NODES];
__device__ float g_h   [N_NODES * 12];
__device__ float g_acc [N_NODES * 12];
__device__ float g_X0  [NB * 12  * NT];
__device__ float g_X1  [NB * 128 * NT];
__device__ float g_X2  [NB * 512 * NT];
__device__ float g_X3  [NB * 128 * NT];
// prepped weights: [tap 0..2 = conv k, 3 = down][COUT][CIN] bf16 hi / lo
__device__ __nv_bfloat16 g_w1h[4 * 512 * 128], g_w1l[4 * 512 * 128];
__device__ __nv_bfloat16 g_w2h[4 * 128 * 512], g_w2l[4 * 128 * 512];

// ---------------- PTX helpers ---------------------------------------------
__device__ __forceinline__ uint32_t smem_u32(const void* p) {
    return (uint32_t)__cvta_generic_to_shared(p);
}
#define LDSM_X4(r0, r1, r2, r3, addr) \
    asm volatile("ldmatrix.sync.aligned.m8n8.x4.shared.b16 {%0,%1,%2,%3}, [%4];" \
        : "=r"(r0), "=r"(r1), "=r"(r2), "=r"(r3) : "r"(addr))
#define MMA16816(d, a, b) \
    asm volatile("mma.sync.aligned.m16n8k16.row.col.f32.bf16.bf16.f32 " \
        "{%0,%1,%2,%3}, {%4,%5,%6,%7}, {%8,%9}, {%0,%1,%2,%3};" \
        : "+f"((d)[0]), "+f"((d)[1]), "+f"((d)[2]), "+f"((d)[3]) \
        : "r"((a)[0]), "r"((a)[1]), "r"((a)[2]), "r"((a)[3]), \
          "r"((b)[0]), "r"((b)[1]))

// ---------------- GCN ------------------------------------------------------
__global__ void k_init_deg() {
    int i = blockIdx.x * blockDim.x + threadIdx.x;
    if (i < N_NODES) g_deg[i] = 1.0f;   // self-loop
}

// edge_index is int32 (JAX x64 disabled downcasts jnp.int64 -> int32)
__global__ void k_count(const int* __restrict__ ei) {
    int e = blockIdx.x * blockDim.x + threadIdx.x;
    if (e < E_EDGES) {
        int dst = ei[E_EDGES + e];
        atomicAdd(&g_deg[dst], 1.0f);
    }
}

__global__ void k_h(const float* __restrict__ x, const float* __restrict__ w) {
    int n = blockIdx.x * blockDim.x + threadIdx.x;
    if (n >= N_NODES) return;
    float xv[12];
#pragma unroll
    for (int j = 0; j < 12; j++) xv[j] = x[n * 12 + j];
    float dinv = rsqrtf(g_deg[n]);
    g_dinv[n] = dinv;
    float s = dinv * dinv;
#pragma unroll
    for (int c = 0; c < 12; c++) {
        float acc = 0.f;
#pragma unroll
        for (int j = 0; j < 12; j++) acc += xv[j] * __ldg(&w[c * 12 + j]);
        g_h[n * 12 + c]   = acc;
        g_acc[n * 12 + c] = s * acc;    // self-loop contribution
    }
}

__global__ void k_scatter(const int* __restrict__ ei) {
    int e = blockIdx.x * blockDim.x + threadIdx.x;
    if (e >= E_EDGES) return;
    int src = ei[e];
    int dst = ei[E_EDGES + e];
    float norm = g_dinv[src] * g_dinv[dst];
    const float4* hs = (const float4*)&g_h[src * 12];
    float4 a = hs[0], b = hs[1], c = hs[2];
    float* ad = &g_acc[dst * 12];
    atomicAdd(ad + 0,  norm * a.x);  atomicAdd(ad + 1,  norm * a.y);
    atomicAdd(ad + 2,  norm * a.z);  atomicAdd(ad + 3,  norm * a.w);
    atomicAdd(ad + 4,  norm * b.x);  atomicAdd(ad + 5,  norm * b.y);
    atomicAdd(ad + 6,  norm * b.z);  atomicAdd(ad + 7,  norm * b.w);
    atomicAdd(ad + 8,  norm * c.x);  atomicAdd(ad + 9,  norm * c.y);
    atomicAdd(ad + 10, norm * c.z);  atomicAdd(ad + 11, norm * c.w);
}

// node-major [n][c] -> [b][c][t] layout for TCN, add bias
__global__ void k_trans(const float* __restrict__ gb) {
    int i = blockIdx.x * blockDim.x + threadIdx.x;
    if (i >= NB * 12 * NT) return;
    int b = i / (12 * NT);
    int r = i - b * 12 * NT;
    int c = r / NT;
    int t = r - c * NT;
    g_X0[i] = g_acc[(b * NT + t) * 12 + c] + gb[c];
}

// ---------------- weight prep: fp32 -> bf16 hi/lo, [tap][co][ci] ----------
template <int COUT, int CIN>
__global__ void k_wprep(const float* __restrict__ cw, const float* __restrict__ dw,
                        __nv_bfloat16* __restrict__ wh, __nv_bfloat16* __restrict__ wl) {
    int e = blockIdx.x * blockDim.x + threadIdx.x;
    if (e >= COUT * CIN) return;
#pragma unroll
    for (int tap = 0; tap < 3; tap++) {
        float w = cw[e * 3 + tap];
        __nv_bfloat16 h = __float2bfloat16(w);
        wh[tap * COUT * CIN + e] = h;
        wl[tap * COUT * CIN + e] = __float2bfloat16(w - __bfloat162float(h));
    }
    float w = dw[e];
    __nv_bfloat16 h = __float2bfloat16(w);
    wh[3 * COUT * CIN + e] = h;
    wl[3 * COUT * CIN + e] = __float2bfloat16(w - __bfloat162float(h));
}

// ---------------- TCN block via mma.sync bf16 (hi/lo split) ---------------
// Per CTA: M=64 co, N=128 = 4 batches x 32 padded t.  16 warps (4m x 4n),
// warp tile M16 x N32.  4 accumulators: Y0,Y1,Y2 (conv taps on UNSHIFTED X)
// and D (downsample).  Epilogue combines with causal shifts:
//   out[t] = relu( relu(Y0[t-2d]+Y1[t-d]+Y2[t]+cb) + D[t]+db )
template <int CIN, int COUT, int DIL>
__global__ void __launch_bounds__(512, 1)
k_tcn_mma(const float* __restrict__ Xin,
          const __nv_bfloat16* __restrict__ wh, const __nv_bfloat16* __restrict__ wl,
          const float* __restrict__ cb, const float* __restrict__ db,
          float* __restrict__ Xout) {
    extern __shared__ char smraw[];
    float* Xr = (float*)smraw;                                   // [4][32][30] fp32
    __nv_bfloat16* As = (__nv_bfloat16*)(smraw + 15360);         // [4 tap][2 hl][64 m][40 k]
    __nv_bfloat16* Bs = (__nv_bfloat16*)(smraw + 15360 + 40960); // [2 hl][128 n][40 k]
    float* Ysm = (float*)smraw;                                  // epilogue alias [4][64][132]

    const int tid  = threadIdx.x;
    const int lane = tid & 31, wid = tid >> 5;
    const int mw = wid & 3, nw = wid >> 2;      // 4x4 warp grid
    const int m0 = mw * 16, n0 = nw * 32;
    const int co0 = blockIdx.y * 64;
    const int b0  = blockIdx.x * 4;

    float acc[4][4][4];                         // [accum][n-tile][reg]
#pragma unroll
    for (int a = 0; a < 4; a++)
#pragma unroll
        for (int n = 0; n < 4; n++)
#pragma unroll
            for (int r = 0; r < 4; r++) acc[a][n][r] = 0.f;

    // ldmatrix address components (canonical recipes)
    const int a_row = m0 + (lane & 15);
    const int a_col = (lane >> 4) * 8;
    const int b_row = (lane & 7) + ((lane >> 4) << 3);
    const int b_col = ((lane >> 3) & 1) * 8;

    for (int ci0 = 0; ci0 < CIN; ci0 += 32) {
        __syncthreads();
        // stage raw X chunk (coalesced): [b][ci][t]
        for (int e = tid; e < 4 * 32 * 30; e += 512) {
            int b = e / 960, r = e - b * 960, ci = r / 30, t = r - ci * 30;
            Xr[e] = Xin[(long)(b0 + b) * CIN * NT + (long)(ci0 + ci) * NT + t];
        }
        // stage A (4 taps, hi+lo), coalesced 64B rows
        for (int e = tid; e < 4 * 64 * 32; e += 512) {
            int tap = e >> 11, r = e & 2047, m = r >> 5, k = r & 31;
            long gi = (long)tap * COUT * CIN + (long)(co0 + m) * CIN + ci0 + k;
            As[(tap * 2 + 0) * 2560 + m * 40 + k] = wh[gi];
            As[(tap * 2 + 1) * 2560 + m * 40 + k] = wl[gi];
        }
        __syncthreads();
        // build B [n][k] (n = b*32 + t, k = ci) with hi/lo split
        for (int e = tid; e < 128 * 32; e += 512) {
            int n = e >> 5, k = e & 31;
            int b = n >> 5, t = n & 31;
            float x = (t < NT) ? Xr[(b * 32 + k) * 30 + t] : 0.0f;
            __nv_bfloat16 h = __float2bfloat16(x);
            Bs[n * 40 + k]        = h;
            Bs[5120 + n * 40 + k] = __float2bfloat16(x - __bfloat162float(h));
        }
        __syncthreads();
#pragma unroll
        for (int ks = 0; ks < 2; ks++) {
            const int k0 = ks * 16;
            uint32_t bh[4][2], bl[4][2];
#pragma unroll
            for (int j = 0; j < 2; j++) {
                uint32_t ad = smem_u32(&Bs[(n0 + j * 16 + b_row) * 40 + b_col + k0]);
                LDSM_X4(bh[2 * j][0], bh[2 * j][1], bh[2 * j + 1][0], bh[2 * j + 1][1], ad);
                ad = smem_u32(&Bs[5120 + (n0 + j * 16 + b_row) * 40 + b_col + k0]);
                LDSM_X4(bl[2 * j][0], bl[2 * j][1], bl[2 * j + 1][0], bl[2 * j + 1][1], ad);
            }
#pragma unroll
            for (int tap = 0; tap < 4; tap++) {
                uint32_t ah[4], al[4];
                LDSM_X4(ah[0], ah[1], ah[2], ah[3],
                        smem_u32(&As[(tap * 2 + 0) * 2560 + a_row * 40 + a_col + k0]));
                LDSM_X4(al[0], al[1], al[2], al[3],
                        smem_u32(&As[(tap * 2 + 1) * 2560 + a_row * 40 + a_col + k0]));
#pragma unroll
                for (int nt = 0; nt < 4; nt++) {
                    MMA16816(acc[tap][nt], ah, bh[nt]);
                    MMA16816(acc[tap][nt], ah, bl[nt]);
                    MMA16816(acc[tap][nt], al, bh[nt]);
                }
            }
        }
    }

    __syncthreads();                 // mainloop smem dead; alias as Y
    // write accumulators to smem [accum][64 co][132 n]
    {
        const int row = m0 + (lane >> 2);
        const int colb = n0 + 2 * (lane & 3);
#pragma unroll
        for (int tap = 0; tap < 4; tap++) {
            float* yb = &Ysm[tap * 64 * 132];
#pragma unroll
            for (int nt = 0; nt < 4; nt++) {
                int col = colb + nt * 8;
                *(float2*)&yb[row * 132 + col]       = make_float2(acc[tap][nt][0], acc[tap][nt][1]);
                *(float2*)&yb[(row + 8) * 132 + col] = make_float2(acc[tap][nt][2], acc[tap][nt][3]);
            }
        }
    }
    __syncthreads();
    // shifted combine + store (coalesced along t)
    for (int e = tid; e < 64 * 128; e += 512) {
        int co = e >> 7, n = e & 127;
        int b = n >> 5, t = n & 31;
        if (t >= NT) continue;
        float y2 = Ysm[2 * 8448 + co * 132 + n];
        float y1 = (t >= DIL)     ? Ysm[1 * 8448 + co * 132 + n - DIL]     : 0.f;
        float y0 = (t >= 2 * DIL) ? Ysm[0 * 8448 + co * 132 + n - 2 * DIL] : 0.f;
        float dv = Ysm[3 * 8448 + co * 132 + n];
        float o = fmaxf(fmaxf(y0 + y1 + y2 + cb[co0 + co], 0.f) + dv + db[co0 + co], 0.f);
        Xout[(long)(b0 + b) * COUT * NT + (long)(co0 + co) * NT + t] = o;
    }
}

// ---------------- block0: small scalar TCN (CIN=12) ------------------------
template <int CIN, int COUT, int DIL, int G, int CICH>
__global__ void k_tcn(const float* __restrict__ Xin,
                      const float* __restrict__ cw, const float* __restrict__ cb,
                      const float* __restrict__ dw, const float* __restrict__ db,
                      float* __restrict__ Xout) {
    extern __shared__ float sm[];
    float* ws = sm;                       // [CICH][4][128]
    float* xs = sm + CICH * 4 * 128;      // [G][CICH][NT]
    const int tid  = threadIdx.x;
    const int cow  = tid & 127;
    const int g    = tid >> 7;
    const int co   = blockIdx.y * 128 + cow;
    const int b0   = blockIdx.x * G;
    const int NTH  = 128 * G;

    float accC[NT], accD[NT];
#pragma unroll
    for (int t = 0; t < NT; t++) { accC[t] = 0.f; accD[t] = 0.f; }

    for (int ci0 = 0; ci0 < CIN; ci0 += CICH) {
        __syncthreads();
        for (int e = tid; e < 128 * CICH * 3; e += NTH) {
            int co_ = e / (CICH * 3);
            int r   = e - co_ * (CICH * 3);
            int ci  = r / 3, k = r - ci * 3;
            ws[(ci * 4 + k) * 128 + co_] =
                cw[((blockIdx.y * 128 + co_) * CIN + ci0 + ci) * 3 + k];
        }
        for (int e = tid; e < 128 * CICH; e += NTH) {
            int co_ = e / CICH;
            int ci  = e - co_ * CICH;
            ws[(ci * 4 + 3) * 128 + co_] =
                dw[(blockIdx.y * 128 + co_) * CIN + ci0 + ci];
        }
        for (int e = tid; e < G * CICH * NT; e += NTH) {
            int g_ = e / (CICH * NT);
            int r  = e - g_ * (CICH * NT);
            int ci = r / NT, t = r - ci * NT;
            xs[e] = Xin[(long)(b0 + g_) * CIN * NT + (ci0 + ci) * NT + t];
        }
        __syncthreads();

#pragma unroll 2
        for (int ci = 0; ci < CICH; ci++) {
            float w0 = ws[(ci * 4 + 0) * 128 + cow];
            float w1 = ws[(ci * 4 + 1) * 128 + cow];
            float w2 = ws[(ci * 4 + 2) * 128 + cow];
            float wd = ws[(ci * 4 + 3) * 128 + cow];
            const float* xr = &xs[(g * CICH + ci) * NT];
#pragma unroll
            for (int t = 0; t < NT; t++) {
                float xv = xr[t];
                accD[t] += wd * xv;
                accC[t] += w2 * xv;
                if (t + DIL     < NT) accC[t + DIL]     += w1 * xv;
                if (t + 2 * DIL < NT) accC[t + 2 * DIL] += w0 * xv;
            }
        }
    }

    float cbv = cb[co], dbv = db[co];
    float* out = &Xout[(long)(b0 + g) * COUT * NT + co * NT];
#pragma unroll
    for (int t = 0; t < NT; t++) {
        float v = fmaxf(accC[t] + cbv, 0.0f) + accD[t] + dbv;
        out[t] = fmaxf(v, 0.0f);
    }
}

// ---------------- FC -------------------------------------------------------
__global__ void k_fc(const float* __restrict__ X, const float* __restrict__ fw,
                     const float* __restrict__ fb, float* __restrict__ out) {
    extern __shared__ float xs[];            // [8][3840]
    const int tid = threadIdx.x;
    const int b0  = blockIdx.x * 8;
    for (int e = tid; e < 8 * 3840; e += 256)
        xs[e] = X[(long)b0 * 3840 + e];
    __syncthreads();

    const int w    = tid >> 5;
    const int lane = tid & 31;
    const int o0   = w * 9;
    float acc[9][8];
#pragma unroll
    for (int r = 0; r < 9; r++)
#pragma unroll
        for (int g2 = 0; g2 < 8; g2++) acc[r][g2] = 0.f;

    for (int it = 0; it < 120; it++) {
        int j = it * 32 + lane;
        float xj[8];
#pragma unroll
        for (int g2 = 0; g2 < 8; g2++) xj[g2] = xs[g2 * 3840 + j];
#pragma unroll
        for (int r = 0; r < 9; r++) {
            float wv = fw[(o0 + r) * 3840 + j];
#pragma unroll
            for (int g2 = 0; g2 < 8; g2++) acc[r][g2] += wv * xj[g2];
        }
    }
#pragma unroll
    for (int r = 0; r < 9; r++) {
#pragma unroll
        for (int g2 = 0; g2 < 8; g2++) {
            float v = acc[r][g2];
            for (int off = 16; off; off >>= 1)
                v += __shfl_xor_sync(0xffffffff, v, off);
            if (lane == 0)
                out[(b0 + g2) * 72 + o0 + r] = v + fb[o0 + r];
        }
    }
}

// ---------------- launch ---------------------------------------------------
extern "C" void kernel_launch(void* const* d_in, const int* in_sizes, int n_in,
                              void* d_out, int out_size) {
    const float* x   = (const float*)d_in[0];
    const int*   ei  = (const int*)d_in[1];     // int32
    const float* gw  = (const float*)d_in[2];
    const float* gb  = (const float*)d_in[3];
    const float* cw0 = (const float*)d_in[4];
    const float* cb0 = (const float*)d_in[5];
    const float* dw0 = (const float*)d_in[6];
    const float* db0 = (const float*)d_in[7];
    const float* cw1 = (const float*)d_in[8];
    const float* cb1 = (const float*)d_in[9];
    const float* dw1 = (const float*)d_in[10];
    const float* db1 = (const float*)d_in[11];
    const float* cw2 = (const float*)d_in[12];
    const float* cb2 = (const float*)d_in[13];
    const float* dw2 = (const float*)d_in[14];
    const float* db2 = (const float*)d_in[15];
    const float* fw  = (const float*)d_in[16];
    const float* fb  = (const float*)d_in[17];
    float* out = (float*)d_out;

    float *pX0, *pX1, *pX2, *pX3;
    cudaGetSymbolAddress((void**)&pX0, g_X0);
    cudaGetSymbolAddress((void**)&pX1, g_X1);
    cudaGetSymbolAddress((void**)&pX2, g_X2);
    cudaGetSymbolAddress((void**)&pX3, g_X3);
    __nv_bfloat16 *pW1h, *pW1l, *pW2h, *pW2l;
    cudaGetSymbolAddress((void**)&pW1h, g_w1h);
    cudaGetSymbolAddress((void**)&pW1l, g_w1l);
    cudaGetSymbolAddress((void**)&pW2h, g_w2h);
    cudaGetSymbolAddress((void**)&pW2l, g_w2l);

    const int smem0 = (12 * 4 * 128 + 4 * 12 * NT) * 4;   // 30336
    const int smemM = 4 * 64 * 132 * 4;                    // 135168 (epilogue max)
    const int smemF = 8 * 3840 * 4;                        // 122880
    cudaFuncSetAttribute(k_tcn_mma<128, 512, 3>,
                         cudaFuncAttributeMaxDynamicSharedMemorySize, smemM);
    cudaFuncSetAttribute(k_tcn_mma<512, 128, 9>,
                         cudaFuncAttributeMaxDynamicSharedMemorySize, smemM);
    cudaFuncSetAttribute(k_fc,
                         cudaFuncAttributeMaxDynamicSharedMemorySize, smemF);

    // ---- GCN ----
    k_init_deg<<<(N_NODES + 255) / 256, 256>>>();
    k_count<<<(E_EDGES + 255) / 256, 256>>>(ei);
    k_h<<<(N_NODES + 255) / 256, 256>>>(x, gw);
    k_scatter<<<(E_EDGES + 255) / 256, 256>>>(ei);
    k_trans<<<(NB * 12 * NT + 255) / 256, 256>>>(gb);

    // ---- weight prep (bf16 hi/lo) ----
    k_wprep<512, 128><<<(512 * 128 + 255) / 256, 256>>>(cw1, dw1, pW1h, pW1l);
    k_wprep<128, 512><<<(128 * 512 + 255) / 256, 256>>>(cw2, dw2, pW2h, pW2l);

    // ---- TCN ----
    k_tcn<12, 128, 1, 4, 12><<<dim3(NB / 4, 1), 512, smem0>>>(pX0, cw0, cb0, dw0, db0, pX1);
    k_tcn_mma<128, 512, 3><<<dim3(NB / 4, 8), 512, smemM>>>(pX1, pW1h, pW1l, cb1, db1, pX2);
    k_tcn_mma<512, 128, 9><<<dim3(NB / 4, 2), 512, smemM>>>(pX2, pW2h, pW2l, cb2, db2, pX3);

    // ---- FC (final relu is identity: X3 >= 0 already) ----
    k_fc<<<NB / 8, 256, smemF>>>(pX3, fw, fb, out);
}

// round 17
// speedup vs baseline: 2.7931x; 1.5243x over previous
#include <cuda_runtime.h>
#include <cuda_bf16.h>
#include <cstdint>

#define N_NODES 61440
#define NB      2048
#define NT      30
#define E_EDGES 491520

// ---------------- scratch (device globals; no runtime allocation) ----------
__device__ float g_deg [N_NODES];
__device__ float g_dinv[N_NODES];
__device__ float g_h   [N_NODES * 12];
__device__ float g_acc [N_NODES * 12];
__device__ float g_X0  [NB * 12 * NT];
__device__ float g_X3  [NB * 128 * NT];
// activations in bf16 hi/lo, B-ready layout [b][t][ci]
__device__ __align__(16) __nv_bfloat16 g_X1h[NB * NT * 128], g_X1l[NB * NT * 128];
__device__ __align__(16) __nv_bfloat16 g_X2h[NB * NT * 512], g_X2l[NB * NT * 512];
// prepped weights: [tap 0..2 = conv k, 3 = down][COUT][CIN] bf16 hi / lo
__device__ __align__(16) __nv_bfloat16 g_w1h[4 * 512 * 128], g_w1l[4 * 512 * 128];
__device__ __align__(16) __nv_bfloat16 g_w2h[4 * 128 * 512], g_w2l[4 * 128 * 512];

// ---------------- PTX helpers ---------------------------------------------
__device__ __forceinline__ uint32_t smem_u32(const void* p) {
    return (uint32_t)__cvta_generic_to_shared(p);
}
#define LDSM_X4(r0, r1, r2, r3, addr) \
    asm volatile("ldmatrix.sync.aligned.m8n8.x4.shared.b16 {%0,%1,%2,%3}, [%4];" \
        : "=r"(r0), "=r"(r1), "=r"(r2), "=r"(r3) : "r"(addr))
#define MMA16816(d, a, b) \
    asm volatile("mma.sync.aligned.m16n8k16.row.col.f32.bf16.bf16.f32 " \
        "{%0,%1,%2,%3}, {%4,%5,%6,%7}, {%8,%9}, {%0,%1,%2,%3};" \
        : "+f"((d)[0]), "+f"((d)[1]), "+f"((d)[2]), "+f"((d)[3]) \
        : "r"((a)[0]), "r"((a)[1]), "r"((a)[2]), "r"((a)[3]), \
          "r"((b)[0]), "r"((b)[1]))
#define CP16(dst, src) \
    asm volatile("cp.async.cg.shared.global [%0], [%1], 16;" :: "r"(dst), "l"(src))
#define CP_COMMIT() asm volatile("cp.async.commit_group;")
#define CP_WAIT0()  asm volatile("cp.async.wait_group 0;")
#define CP_WAIT1()  asm volatile("cp.async.wait_group 1;")

// ---------------- GCN ------------------------------------------------------
__global__ void k_init_deg() {
    int i = blockIdx.x * blockDim.x + threadIdx.x;
    if (i < N_NODES) g_deg[i] = 1.0f;   // self-loop
}

// edge_index is int32 (JAX x64 disabled downcasts jnp.int64 -> int32)
__global__ void k_count(const int* __restrict__ ei) {
    int e = blockIdx.x * blockDim.x + threadIdx.x;
    if (e < E_EDGES) {
        int dst = ei[E_EDGES + e];
        atomicAdd(&g_deg[dst], 1.0f);
    }
}

__global__ void k_h(const float* __restrict__ x, const float* __restrict__ w) {
    int n = blockIdx.x * blockDim.x + threadIdx.x;
    if (n >= N_NODES) return;
    float xv[12];
#pragma unroll
    for (int j = 0; j < 12; j++) xv[j] = x[n * 12 + j];
    float dinv = rsqrtf(g_deg[n]);
    g_dinv[n] = dinv;
    float s = dinv * dinv;
#pragma unroll
    for (int c = 0; c < 12; c++) {
        float acc = 0.f;
#pragma unroll
        for (int j = 0; j < 12; j++) acc += xv[j] * __ldg(&w[c * 12 + j]);
        g_h[n * 12 + c]   = acc;
        g_acc[n * 12 + c] = s * acc;    // self-loop contribution
    }
}

__global__ void k_scatter(const int* __restrict__ ei) {
    int e = blockIdx.x * blockDim.x + threadIdx.x;
    if (e >= E_EDGES) return;
    int src = ei[e];
    int dst = ei[E_EDGES + e];
    float norm = g_dinv[src] * g_dinv[dst];
    const float4* hs = (const float4*)&g_h[src * 12];
    float4 a = hs[0], b = hs[1], c = hs[2];
    float* ad = &g_acc[dst * 12];
    atomicAdd(ad + 0,  norm * a.x);  atomicAdd(ad + 1,  norm * a.y);
    atomicAdd(ad + 2,  norm * a.z);  atomicAdd(ad + 3,  norm * a.w);
    atomicAdd(ad + 4,  norm * b.x);  atomicAdd(ad + 5,  norm * b.y);
    atomicAdd(ad + 6,  norm * b.z);  atomicAdd(ad + 7,  norm * b.w);
    atomicAdd(ad + 8,  norm * c.x);  atomicAdd(ad + 9,  norm * c.y);
    atomicAdd(ad + 10, norm * c.z);  atomicAdd(ad + 11, norm * c.w);
}

// node-major [n][c] -> [b][c][t] layout for TCN, add bias
__global__ void k_trans(const float* __restrict__ gb) {
    int i = blockIdx.x * blockDim.x + threadIdx.x;
    if (i >= NB * 12 * NT) return;
    int b = i / (12 * NT);
    int r = i - b * 12 * NT;
    int c = r / NT;
    int t = r - c * NT;
    g_X0[i] = g_acc[(b * NT + t) * 12 + c] + gb[c];
}

// ---------------- weight prep: fp32 -> bf16 hi/lo, [tap][co][ci] ----------
template <int COUT, int CIN>
__global__ void k_wprep(const float* __restrict__ cw, const float* __restrict__ dw,
                        __nv_bfloat16* __restrict__ wh, __nv_bfloat16* __restrict__ wl) {
    int e = blockIdx.x * blockDim.x + threadIdx.x;
    if (e >= COUT * CIN) return;
#pragma unroll
    for (int tap = 0; tap < 3; tap++) {
        float w = cw[e * 3 + tap];
        __nv_bfloat16 h = __float2bfloat16(w);
        wh[tap * COUT * CIN + e] = h;
        wl[tap * COUT * CIN + e] = __float2bfloat16(w - __bfloat162float(h));
    }
    float w = dw[e];
    __nv_bfloat16 h = __float2bfloat16(w);
    wh[3 * COUT * CIN + e] = h;
    wl[3 * COUT * CIN + e] = __float2bfloat16(w - __bfloat162float(h));
}

// ---------------- block0: scalar TCN 12->128, outputs bf16 hi/lo [b][t][co]
__global__ void __launch_bounds__(512, 1)
k_tcn0(const float* __restrict__ Xin,
       const float* __restrict__ cw, const float* __restrict__ cb,
       const float* __restrict__ dw, const float* __restrict__ db,
       __nv_bfloat16* __restrict__ Xh, __nv_bfloat16* __restrict__ Xl) {
    extern __shared__ float sm[];
    float* ws = sm;                 // [12][4][128] : k0,k1,k2,down
    float* xs = sm + 12 * 4 * 128;  // [4][12][30]
    const int tid = threadIdx.x;
    const int cow = tid & 127;
    const int g   = tid >> 7;
    const int b0  = blockIdx.x * 4;

    for (int e = tid; e < 128 * 12 * 3; e += 512) {
        int co_ = e / 36, r = e - co_ * 36, ci = r / 3, k = r - ci * 3;
        ws[(ci * 4 + k) * 128 + co_] = cw[(co_ * 12 + ci) * 3 + k];
    }
    for (int e = tid; e < 128 * 12; e += 512) {
        int co_ = e / 12, ci = e - co_ * 12;
        ws[(ci * 4 + 3) * 128 + co_] = dw[co_ * 12 + ci];
    }
    for (int e = tid; e < 4 * 12 * NT; e += 512) {
        int g_ = e / (12 * NT), r = e - g_ * (12 * NT), ci = r / NT, t = r - ci * NT;
        xs[e] = Xin[(long)(b0 + g_) * 12 * NT + ci * NT + t];
    }
    __syncthreads();

    float accC[NT], accD[NT];
#pragma unroll
    for (int t = 0; t < NT; t++) { accC[t] = 0.f; accD[t] = 0.f; }
#pragma unroll
    for (int ci = 0; ci < 12; ci++) {
        float w0 = ws[(ci * 4 + 0) * 128 + cow];
        float w1 = ws[(ci * 4 + 1) * 128 + cow];
        float w2 = ws[(ci * 4 + 2) * 128 + cow];
        float wd = ws[(ci * 4 + 3) * 128 + cow];
        const float* xr = &xs[(g * 12 + ci) * NT];
#pragma unroll
        for (int t = 0; t < NT; t++) {
            float xv = xr[t];
            accD[t] += wd * xv;
            accC[t] += w2 * xv;
            if (t + 1 < NT) accC[t + 1] += w1 * xv;
            if (t + 2 < NT) accC[t + 2] += w0 * xv;
        }
    }
    float cbv = cb[cow], dbv = db[cow];
#pragma unroll
    for (int t = 0; t < NT; t++) {
        float o = fmaxf(fmaxf(accC[t] + cbv, 0.f) + accD[t] + dbv, 0.f);
        __nv_bfloat16 h = __float2bfloat16(o);
        long idx = ((long)(b0 + g) * NT + t) * 128 + cow;
        Xh[idx] = h;
        Xl[idx] = __float2bfloat16(o - __bfloat162float(h));
    }
}

// ---------------- TCN block via mma.sync, cp.async double-buffered ---------
// B input pre-split bf16 hi/lo in [b][t][CIN].  4 accumulators (3 taps on
// UNSHIFTED X + downsample), shifted combine in epilogue.
// CTA: M=64 co x N=128 (4 batches x 32 padded t), 16 warps (4m x 4n).
template <int CIN, int COUT, int DIL, bool OB>
__global__ void __launch_bounds__(512, 1)
k_mma(const __nv_bfloat16* __restrict__ Xbh, const __nv_bfloat16* __restrict__ Xbl,
      const __nv_bfloat16* __restrict__ wh,  const __nv_bfloat16* __restrict__ wl,
      const float* __restrict__ cb, const float* __restrict__ db,
      float* __restrict__ Xout,
      __nv_bfloat16* __restrict__ Xoh, __nv_bfloat16* __restrict__ Xol) {
    constexpr int NC = CIN / 32;
    extern __shared__ char smraw[];
    __nv_bfloat16* As = (__nv_bfloat16*)smraw;            // [2 buf][512 rows][40]
    __nv_bfloat16* Bs = (__nv_bfloat16*)(smraw + 81920);  // [2 buf][256 rows][40]
    float* Ysm = (float*)smraw;                           // epilogue alias [4][64][132]

    const int tid  = threadIdx.x;
    const int lane = tid & 31, wid = tid >> 5;
    const int mw = wid & 3, nw = wid >> 2;
    const int m0 = mw * 16, n0 = nw * 32;
    const int co0 = blockIdx.y * 64;
    const int b0  = blockIdx.x * 4;

    // zero the padded-t B rows once (t = 30, 31; both hl, both buffers)
    for (int e = tid; e < 32 * 40; e += 512) {
        int r2 = e / 40, k = e - r2 * 40;
        int buf = r2 >> 4, rr = r2 & 15, hl = rr >> 3, rrr = rr & 7;
        int b = rrr >> 1, t = 30 + (rrr & 1);
        Bs[buf * 10240 + (hl * 128 + b * 32 + t) * 40 + k] = __float2bfloat16(0.f);
    }

    float acc[4][4][4];
#pragma unroll
    for (int a = 0; a < 4; a++)
#pragma unroll
        for (int n = 0; n < 4; n++)
#pragma unroll
            for (int r = 0; r < 4; r++) acc[a][n][r] = 0.f;

    const int a_row = m0 + (lane & 15);
    const int a_col = (lane >> 4) * 8;
    const int b_row = (lane & 7) + ((lane >> 4) << 3);
    const int b_col = ((lane >> 3) & 1) * 8;

    auto stage = [&](int c, int buf) {
        const int ci0 = c * 32;
        // A: 4 tap x 2 hl x 64 m rows of 64B  (512 rows x 4 segs)
        for (int s = tid; s < 2048; s += 512) {
            int row = s >> 2, seg = s & 3;
            int tap = row >> 7, hl = (row >> 6) & 1, m = row & 63;
            const __nv_bfloat16* src =
                (hl ? wl : wh) + ((long)tap * COUT + co0 + m) * CIN + ci0 + seg * 8;
            CP16(smem_u32(As + buf * 20480 + row * 40 + seg * 8), src);
        }
        // B: 2 hl x 4 b x 30 t rows of 64B  (240 rows x 4 segs)
        for (int s = tid; s < 960; s += 512) {
            int row = s >> 2, seg = s & 3;
            int hl = row / 120, r = row - hl * 120, b = r / 30, t = r - b * 30;
            const __nv_bfloat16* src =
                (hl ? Xbl : Xbh) + ((long)(b0 + b) * NT + t) * CIN + ci0 + seg * 8;
            CP16(smem_u32(Bs + buf * 10240 + (hl * 128 + b * 32 + t) * 40 + seg * 8), src);
        }
        CP_COMMIT();
    };

    stage(0, 0);
    for (int c = 0; c < NC; c++) {
        const int buf = c & 1;
        if (c + 1 < NC) { stage(c + 1, (c + 1) & 1); CP_WAIT1(); }
        else           { CP_WAIT0(); }
        __syncthreads();

        const __nv_bfloat16* Ab = As + buf * 20480;
        const __nv_bfloat16* Bb = Bs + buf * 10240;
#pragma unroll
        for (int ks = 0; ks < 2; ks++) {
            const int k0 = ks * 16;
            uint32_t bh[4][2], bl[4][2];
#pragma unroll
            for (int j = 0; j < 2; j++) {
                uint32_t ad = smem_u32(&Bb[(n0 + j * 16 + b_row) * 40 + b_col + k0]);
                LDSM_X4(bh[2 * j][0], bh[2 * j][1], bh[2 * j + 1][0], bh[2 * j + 1][1], ad);
                ad = smem_u32(&Bb[5120 + (n0 + j * 16 + b_row) * 40 + b_col + k0]);
                LDSM_X4(bl[2 * j][0], bl[2 * j][1], bl[2 * j + 1][0], bl[2 * j + 1][1], ad);
            }
#pragma unroll
            for (int tap = 0; tap < 4; tap++) {
                uint32_t ah[4], al[4];
                LDSM_X4(ah[0], ah[1], ah[2], ah[3],
                        smem_u32(&Ab[(tap * 2 + 0) * 2560 + a_row * 40 + a_col + k0]));
                LDSM_X4(al[0], al[1], al[2], al[3],
                        smem_u32(&Ab[(tap * 2 + 1) * 2560 + a_row * 40 + a_col + k0]));
#pragma unroll
                for (int nt = 0; nt < 4; nt++) {
                    MMA16816(acc[tap][nt], ah, bh[nt]);
                    MMA16816(acc[tap][nt], ah, bl[nt]);
                    MMA16816(acc[tap][nt], al, bh[nt]);
                }
            }
        }
        __syncthreads();
    }

    // write accumulators to smem [accum][64 co][132 n]
    {
        const int row = m0 + (lane >> 2);
        const int colb = n0 + 2 * (lane & 3);
#pragma unroll
        for (int tap = 0; tap < 4; tap++) {
            float* yb = &Ysm[tap * 64 * 132];
#pragma unroll
            for (int nt = 0; nt < 4; nt++) {
                int col = colb + nt * 8;
                *(float2*)&yb[row * 132 + col]       = make_float2(acc[tap][nt][0], acc[tap][nt][1]);
                *(float2*)&yb[(row + 8) * 132 + col] = make_float2(acc[tap][nt][2], acc[tap][nt][3]);
            }
        }
    }
    __syncthreads();
    // shifted combine + store
    if (OB) {
        // bf16 hi/lo out, layout [b][t][COUT]; iterate co-fastest for coalescing
        for (int e = tid; e < 64 * 128; e += 512) {
            int co = e & 63, n = e >> 6;
            int b = n >> 5, t = n & 31;
            if (t >= NT) continue;
            float y2 = Ysm[2 * 8448 + co * 132 + n];
            float y1 = (t >= DIL)     ? Ysm[1 * 8448 + co * 132 + n - DIL]     : 0.f;
            float y0 = (t >= 2 * DIL) ? Ysm[0 * 8448 + co * 132 + n - 2 * DIL] : 0.f;
            float dv = Ysm[3 * 8448 + co * 132 + n];
            float o = fmaxf(fmaxf(y0 + y1 + y2 + cb[co0 + co], 0.f) + dv + db[co0 + co], 0.f);
            __nv_bfloat16 h = __float2bfloat16(o);
            long idx = ((long)(b0 + b) * NT + t) * COUT + co0 + co;
            Xoh[idx] = h;
            Xol[idx] = __float2bfloat16(o - __bfloat162float(h));
        }
    } else {
        // fp32 out, layout [b][co][t] (fc consumes this)
        for (int e = tid; e < 64 * 128; e += 512) {
            int co = e >> 7, n = e & 127;
            int b = n >> 5, t = n & 31;
            if (t >= NT) continue;
            float y2 = Ysm[2 * 8448 + co * 132 + n];
            float y1 = (t >= DIL)     ? Ysm[1 * 8448 + co * 132 + n - DIL]     : 0.f;
            float y0 = (t >= 2 * DIL) ? Ysm[0 * 8448 + co * 132 + n - 2 * DIL] : 0.f;
            float dv = Ysm[3 * 8448 + co * 132 + n];
            float o = fmaxf(fmaxf(y0 + y1 + y2 + cb[co0 + co], 0.f) + dv + db[co0 + co], 0.f);
            Xout[(long)(b0 + b) * COUT * NT + (long)(co0 + co) * NT + t] = o;
        }
    }
}

// ---------------- FC -------------------------------------------------------
__global__ void k_fc(const float* __restrict__ X, const float* __restrict__ fw,
                     const float* __restrict__ fb, float* __restrict__ out) {
    extern __shared__ float xs[];            // [8][3840]
    const int tid = threadIdx.x;
    const int b0  = blockIdx.x * 8;
    for (int e = tid; e < 8 * 3840; e += 256)
        xs[e] = X[(long)b0 * 3840 + e];
    __syncthreads();

    const int w    = tid >> 5;
    const int lane = tid & 31;
    const int o0   = w * 9;
    float acc[9][8];
#pragma unroll
    for (int r = 0; r < 9; r++)
#pragma unroll
        for (int g2 = 0; g2 < 8; g2++) acc[r][g2] = 0.f;

    for (int it = 0; it < 120; it++) {
        int j = it * 32 + lane;
        float xj[8];
#pragma unroll
        for (int g2 = 0; g2 < 8; g2++) xj[g2] = xs[g2 * 3840 + j];
#pragma unroll
        for (int r = 0; r < 9; r++) {
            float wv = fw[(o0 + r) * 3840 + j];
#pragma unroll
            for (int g2 = 0; g2 < 8; g2++) acc[r][g2] += wv * xj[g2];
        }
    }
#pragma unroll
    for (int r = 0; r < 9; r++) {
#pragma unroll
        for (int g2 = 0; g2 < 8; g2++) {
            float v = acc[r][g2];
            for (int off = 16; off; off >>= 1)
                v += __shfl_xor_sync(0xffffffff, v, off);
            if (lane == 0)
                out[(b0 + g2) * 72 + o0 + r] = v + fb[o0 + r];
        }
    }
}

// ---------------- launch ---------------------------------------------------
extern "C" void kernel_launch(void* const* d_in, const int* in_sizes, int n_in,
                              void* d_out, int out_size) {
    const float* x   = (const float*)d_in[0];
    const int*   ei  = (const int*)d_in[1];     // int32
    const float* gw  = (const float*)d_in[2];
    const float* gb  = (const float*)d_in[3];
    const float* cw0 = (const float*)d_in[4];
    const float* cb0 = (const float*)d_in[5];
    const float* dw0 = (const float*)d_in[6];
    const float* db0 = (const float*)d_in[7];
    const float* cw1 = (const float*)d_in[8];
    const float* cb1 = (const float*)d_in[9];
    const float* dw1 = (const float*)d_in[10];
    const float* db1 = (const float*)d_in[11];
    const float* cw2 = (const float*)d_in[12];
    const float* cb2 = (const float*)d_in[13];
    const float* dw2 = (const float*)d_in[14];
    const float* db2 = (const float*)d_in[15];
    const float* fw  = (const float*)d_in[16];
    const float* fb  = (const float*)d_in[17];
    float* out = (float*)d_out;

    float *pX0, *pX3;
    cudaGetSymbolAddress((void**)&pX0, g_X0);
    cudaGetSymbolAddress((void**)&pX3, g_X3);
    __nv_bfloat16 *pX1h, *pX1l, *pX2h, *pX2l, *pW1h, *pW1l, *pW2h, *pW2l;
    cudaGetSymbolAddress((void**)&pX1h, g_X1h);
    cudaGetSymbolAddress((void**)&pX1l, g_X1l);
    cudaGetSymbolAddress((void**)&pX2h, g_X2h);
    cudaGetSymbolAddress((void**)&pX2l, g_X2l);
    cudaGetSymbolAddress((void**)&pW1h, g_w1h);
    cudaGetSymbolAddress((void**)&pW1l, g_w1l);
    cudaGetSymbolAddress((void**)&pW2h, g_w2h);
    cudaGetSymbolAddress((void**)&pW2l, g_w2l);

    const int smem0 = (12 * 4 * 128 + 4 * 12 * NT) * 4;   // 30336
    const int smemM = 4 * 64 * 132 * 4;                    // 135168 (epilogue alias max)
    const int smemF = 8 * 3840 * 4;                        // 122880
    cudaFuncSetAttribute(k_mma<128, 512, 3, true>,
                         cudaFuncAttributeMaxDynamicSharedMemorySize, smemM);
    cudaFuncSetAttribute(k_mma<512, 128, 9, false>,
                         cudaFuncAttributeMaxDynamicSharedMemorySize, smemM);
    cudaFuncSetAttribute(k_fc,
                         cudaFuncAttributeMaxDynamicSharedMemorySize, smemF);

    // ---- GCN ----
    k_init_deg<<<(N_NODES + 255) / 256, 256>>>();
    k_count<<<(E_EDGES + 255) / 256, 256>>>(ei);
    k_h<<<(N_NODES + 255) / 256, 256>>>(x, gw);
    k_scatter<<<(E_EDGES + 255) / 256, 256>>>(ei);
    k_trans<<<(NB * 12 * NT + 255) / 256, 256>>>(gb);

    // ---- weight prep (bf16 hi/lo) ----
    k_wprep<512, 128><<<(512 * 128 + 255) / 256, 256>>>(cw1, dw1, pW1h, pW1l);
    k_wprep<128, 512><<<(128 * 512 + 255) / 256, 256>>>(cw2, dw2, pW2h, pW2l);

    // ---- TCN ----
    k_tcn0<<<NB / 4, 512, smem0>>>(pX0, cw0, cb0, dw0, db0, pX1h, pX1l);
    k_mma<128, 512, 3, true><<<dim3(NB / 4, 8), 512, smemM>>>(
        pX1h, pX1l, pW1h, pW1l, cb1, db1, nullptr, pX2h, pX2l);
    k_mma<512, 128, 9, false><<<dim3(NB / 4, 2), 512, smemM>>>(
        pX2h, pX2l, pW2h, pW2l, cb2, db2, pX3, nullptr, nullptr);

    // ---- FC (final relu is identity: X3 >= 0 already) ----
    k_fc<<<NB / 8, 256, smemF>>>(pX3, fw, fb, out);
}